// round 1
// baseline (speedup 1.0000x reference)
#include <cuda_runtime.h>
#include <cstdint>
#include <cstddef>

// Fixed problem dims (from setup_inputs)
#define TT      65536            // total rows (32 * 2048)
#define DD      256              // feature dim
#define PP      512              // patterns
#define HH      8                // heads
#define DA      64               // head dim
#define LSEQ    2048             // per-sequence length
#define LN_EPS  1e-5f

// ---------------- device scratch (no allocations allowed) ----------------
__device__ float g_wT[3 * DD * DD];            // [k][i][c]   transposed conv weights
__device__ float g_woT[(HH * DA) * DD];        // [j][c]      transposed wout
__device__ float g_xln[(size_t)TT * DD];       // conv+LN output (64 MB)
__device__ float g_q[(size_t)TT * (HH * DA)];  // q           (128 MB)
__device__ float g_att[(size_t)TT * (HH * DA)];// attn output (128 MB)
__device__ float g_kT[HH * DA * PP];           // [h][d][w]   pre-scaled by 1/8
__device__ float g_v[HH * PP * DA];            // [h][w][d]

// ---------------- helpers ----------------
__device__ __forceinline__ float2 blockSum2(float a, float b, float* red) {
    // 256 threads / 8 warps
    #pragma unroll
    for (int o = 16; o; o >>= 1) {
        a += __shfl_xor_sync(0xffffffffu, a, o);
        b += __shfl_xor_sync(0xffffffffu, b, o);
    }
    __syncthreads();  // protect red from reads of a previous call
    if ((threadIdx.x & 31) == 0) {
        red[threadIdx.x >> 5] = a;
        red[(threadIdx.x >> 5) + 8] = b;
    }
    __syncthreads();
    a = 0.f; b = 0.f;
    #pragma unroll
    for (int k = 0; k < 8; k++) { a += red[k]; b += red[k + 8]; }
    return make_float2(a, b);
}

// ---------------- K0: weight transposes ----------------
__global__ void __launch_bounds__(256) k_prep(const float* __restrict__ conv_w,
                                              const float* __restrict__ wout) {
    int idx = blockIdx.x * 256 + threadIdx.x;
    if (idx < 3 * DD * DD) {
        int c = idx / (DD * 3);
        int rem = idx % (DD * 3);
        int i = rem / 3, k = rem % 3;
        g_wT[(k * DD + i) * DD + c] = conv_w[idx];
    }
    if (idx < DD * (HH * DA)) {
        int c = idx >> 9, j = idx & 511;
        g_woT[j * DD + c] = wout[idx];
    }
}

// ---------------- K1: pattern double-LN + kv projection ----------------
// 64 blocks x 256 threads, 8 pattern rows per block
__global__ void __launch_bounds__(256) k_patkv(const float* __restrict__ pattern,
                                               const float* __restrict__ wkv) {
    __shared__ float sp[8][DD];
    __shared__ float red[16];
    int r0 = blockIdx.x * 8;
    int tid = threadIdx.x;

    for (int r = 0; r < 8; r++) {
        float v = pattern[(size_t)(r0 + r) * DD + tid];
        float2 s = blockSum2(v, v * v, red);
        float mu = s.x * (1.f / DD);
        float var = s.y * (1.f / DD) - mu * mu;
        v = (v - mu) * rsqrtf(var + LN_EPS);
        s = blockSum2(v, v * v, red);
        mu = s.x * (1.f / DD);
        var = s.y * (1.f / DD) - mu * mu;
        v = (v - mu) * rsqrtf(var + LN_EPS);
        sp[r][tid] = v;
    }
    __syncthreads();

    for (int m = 0; m < 4; m++) {
        int j = m * 256 + tid;                // 0..1023 output of kv
        float acc[8];
        #pragma unroll
        for (int r = 0; r < 8; r++) acc[r] = 0.f;
        const float* wr = wkv + (size_t)j * DD;
        for (int i = 0; i < DD; i++) {
            float w = wr[i];
            #pragma unroll
            for (int r = 0; r < 8; r++) acc[r] += w * sp[r][i];
        }
        int h = j >> 7, e = j & 127;          // kv.reshape(P, H, 2*dA)
        if (e < DA) {
            #pragma unroll
            for (int r = 0; r < 8; r++)
                g_kT[(h * DA + e) * PP + r0 + r] = 0.125f * acc[r];   // fold scale
        } else {
            int d = e - DA;
            #pragma unroll
            for (int r = 0; r < 8; r++)
                g_v[((size_t)h * PP + r0 + r) * DA + d] = acc[r];
        }
    }
}

// ---------------- K2: causal conv + bias + residual + leaky + LN ----------------
// 2048 blocks x 256 threads, 32 rows per block (blocks never straddle a sequence)
__global__ void __launch_bounds__(256) k_conv(const float* __restrict__ x,
                                              const float* __restrict__ bias) {
    __shared__ float xsT[DD][40];   // [channel][row 0..33], row 0 == t0-2
    __shared__ float red[16];
    int t0 = blockIdx.x * 32;
    int tid = threadIdx.x;
    int seq_start = t0 & ~(LSEQ - 1);

    #pragma unroll
    for (int rr = 0; rr < 34; rr++) {
        int gr = t0 - 2 + rr;
        xsT[tid][rr] = (gr >= seq_start) ? x[(size_t)gr * DD + tid] : 0.f;
    }
    __syncthreads();

    float acc[32];
    #pragma unroll
    for (int r = 0; r < 32; r++) acc[r] = 0.f;

    const float* w0 = g_wT;                 // tap for x[t-2]
    const float* w1 = g_wT + DD * DD;       // tap for x[t-1]
    const float* w2 = g_wT + 2 * DD * DD;   // tap for x[t]

    for (int i = 0; i < DD; i++) {
        float a0 = w0[i * DD + tid];
        float a1 = w1[i * DD + tid];
        float a2 = w2[i * DD + tid];
        float4 xq[9];
        const float4* xp = (const float4*)xsT[i];
        #pragma unroll
        for (int m = 0; m < 9; m++) xq[m] = xp[m];
        const float* xv = (const float*)xq;
        #pragma unroll
        for (int r = 0; r < 32; r++)
            acc[r] += a0 * xv[r] + a1 * xv[r + 1] + a2 * xv[r + 2];
    }

    float bv = bias[tid];
    for (int r = 0; r < 32; r++) {
        float y = acc[r] + bv + xsT[tid][r + 2];   // +bias +residual
        y = (y > 0.f) ? y : 0.01f * y;             // leaky relu
        float2 s = blockSum2(y, y * y, red);
        float mu = s.x * (1.f / DD);
        float var = s.y * (1.f / DD) - mu * mu;
        g_xln[(size_t)(t0 + r) * DD + tid] = (y - mu) * rsqrtf(var + LN_EPS);
    }
}

// ---------------- K3: q = xln @ wq^T  (65536x512, K=256) ----------------
// grid (1024, 8), 64x64 tile, 4x4 micro-tile per thread
__global__ void __launch_bounds__(256) k_q(const float* __restrict__ wq) {
    __shared__ float As[16][68];
    __shared__ float Bs[16][68];
    int bm = blockIdx.x * 64;
    int bn = blockIdx.y * 64;
    int tid = threadIdx.x;
    int tm = (tid >> 4) * 4;
    int tn = (tid & 15) * 4;
    int lr = tid >> 2;
    int lk = (tid & 3) * 4;

    float acc[4][4];
    #pragma unroll
    for (int i = 0; i < 4; i++)
        #pragma unroll
        for (int j = 0; j < 4; j++) acc[i][j] = 0.f;

    for (int k0 = 0; k0 < DD; k0 += 16) {
        float4 av = *(const float4*)&g_xln[(size_t)(bm + lr) * DD + k0 + lk];
        float4 bv = *(const float4*)&wq[(size_t)(bn + lr) * DD + k0 + lk];
        As[lk + 0][lr] = av.x; As[lk + 1][lr] = av.y;
        As[lk + 2][lr] = av.z; As[lk + 3][lr] = av.w;
        Bs[lk + 0][lr] = bv.x; Bs[lk + 1][lr] = bv.y;
        Bs[lk + 2][lr] = bv.z; Bs[lk + 3][lr] = bv.w;
        __syncthreads();
        #pragma unroll
        for (int kk = 0; kk < 16; kk++) {
            float a[4], b[4];
            #pragma unroll
            for (int u = 0; u < 4; u++) a[u] = As[kk][tm + u];
            #pragma unroll
            for (int u = 0; u < 4; u++) b[u] = Bs[kk][tn + u];
            #pragma unroll
            for (int i = 0; i < 4; i++)
                #pragma unroll
                for (int j = 0; j < 4; j++) acc[i][j] += a[i] * b[j];
        }
        __syncthreads();
    }
    #pragma unroll
    for (int i = 0; i < 4; i++)
        #pragma unroll
        for (int j = 0; j < 4; j++)
            g_q[(size_t)(bm + tm + i) * 512 + bn + tn + j] = acc[i][j];
}

// ---------------- K4: fused attention per (32 rows, head) ----------------
// grid (2048, 8) x 256 threads. scores in SMEM (transposed), softmax, attn@V
__global__ void __launch_bounds__(256) k_attn() {
    extern __shared__ float dsm[];
    float* qs  = dsm;                 // [32][64]
    float* ssT = dsm + 32 * 64;       // [512][36]  (scores transposed)

    int r0 = blockIdx.x * 32;
    int h  = blockIdx.y;
    int tid = threadIdx.x;

    for (int idx = tid; idx < 32 * 64; idx += 256) {
        int r = idx >> 6, d = idx & 63;
        qs[r * 64 + d] = g_q[(size_t)(r0 + r) * 512 + h * 64 + d];
    }
    __syncthreads();

    int rq = tid >> 5;     // 0..7  -> rows rq*4 .. rq*4+3
    int wc = tid & 31;
    const float* kT = g_kT + (size_t)h * DA * PP;   // [d][w], pre-scaled

    #pragma unroll 1
    for (int half = 0; half < 2; half++) {
        float acc[4][8];
        #pragma unroll
        for (int i = 0; i < 4; i++)
            #pragma unroll
            for (int j = 0; j < 8; j++) acc[i][j] = 0.f;
        for (int d = 0; d < DA; d++) {
            float q4[4];
            #pragma unroll
            for (int i = 0; i < 4; i++) q4[i] = qs[(rq * 4 + i) * 64 + d];
            const float* kp = kT + d * PP + half * 256 + wc;
            #pragma unroll
            for (int j = 0; j < 8; j++) {
                float kv = kp[j * 32];
                #pragma unroll
                for (int i = 0; i < 4; i++) acc[i][j] += q4[i] * kv;
            }
        }
        #pragma unroll
        for (int j = 0; j < 8; j++) {
            int w = half * 256 + j * 32 + wc;
            #pragma unroll
            for (int i = 0; i < 4; i++) ssT[w * 36 + rq * 4 + i] = acc[i][j];
        }
    }
    __syncthreads();

    // softmax per row over 512 patterns; warp wp handles rows wp*4..+3
    int wp = tid >> 5, lane = tid & 31;
    for (int rr = 0; rr < 4; rr++) {
        int r = wp * 4 + rr;
        float m = -1e30f;
        for (int w = lane; w < PP; w += 32) m = fmaxf(m, ssT[w * 36 + r]);
        #pragma unroll
        for (int o = 16; o; o >>= 1) m = fmaxf(m, __shfl_xor_sync(0xffffffffu, m, o));
        float s = 0.f;
        for (int w = lane; w < PP; w += 32) {
            float e = __expf(ssT[w * 36 + r] - m);
            ssT[w * 36 + r] = e;
            s += e;
        }
        #pragma unroll
        for (int o = 16; o; o >>= 1) s += __shfl_xor_sync(0xffffffffu, s, o);
        float inv = 1.f / s;
        for (int w = lane; w < PP; w += 32) ssT[w * 36 + r] *= inv;
    }
    __syncthreads();

    // attn @ V : thread -> rows rq*4..+3, d in {wc, wc+32}
    const float* vh = g_v + (size_t)h * PP * DA;
    float oacc[4][2];
    #pragma unroll
    for (int i = 0; i < 4; i++) { oacc[i][0] = 0.f; oacc[i][1] = 0.f; }
    for (int w = 0; w < PP; w++) {
        float4 a4 = *(const float4*)&ssT[w * 36 + rq * 4];
        float v0 = vh[w * DA + wc];
        float v1 = vh[w * DA + wc + 32];
        oacc[0][0] += a4.x * v0; oacc[0][1] += a4.x * v1;
        oacc[1][0] += a4.y * v0; oacc[1][1] += a4.y * v1;
        oacc[2][0] += a4.z * v0; oacc[2][1] += a4.z * v1;
        oacc[3][0] += a4.w * v0; oacc[3][1] += a4.w * v1;
    }
    #pragma unroll
    for (int i = 0; i < 4; i++) {
        g_att[(size_t)(r0 + rq * 4 + i) * 512 + h * 64 + wc]      = oacc[i][0];
        g_att[(size_t)(r0 + rq * 4 + i) * 512 + h * 64 + wc + 32] = oacc[i][1];
    }
}

// ---------------- K5: out = att @ wout^T + bout, then LN ----------------
// 2048 blocks x 256 threads, 32 rows per block
__global__ void __launch_bounds__(256) k_out(const float* __restrict__ bout,
                                             float* __restrict__ out) {
    extern __shared__ float asT[];   // [512][36]
    __shared__ float red[16];
    int r0 = blockIdx.x * 32;
    int tid = threadIdx.x;

    for (int idx = tid; idx < 32 * 512; idx += 256) {
        int r = idx >> 9, j = idx & 511;
        asT[j * 36 + r] = g_att[(size_t)(r0 + r) * 512 + j];
    }
    __syncthreads();

    float acc[32];
    #pragma unroll
    for (int r = 0; r < 32; r++) acc[r] = 0.f;

    for (int j = 0; j < 512; j++) {
        float w = g_woT[j * DD + tid];
        const float4* ap = (const float4*)&asT[j * 36];
        #pragma unroll
        for (int m = 0; m < 8; m++) {
            float4 a = ap[m];
            acc[m * 4 + 0] += w * a.x;
            acc[m * 4 + 1] += w * a.y;
            acc[m * 4 + 2] += w * a.z;
            acc[m * 4 + 3] += w * a.w;
        }
    }

    float bv = bout[tid];
    for (int r = 0; r < 32; r++) {
        float y = acc[r] + bv;
        float2 s = blockSum2(y, y * y, red);
        float mu = s.x * (1.f / DD);
        float var = s.y * (1.f / DD) - mu * mu;
        out[(size_t)(r0 + r) * DD + tid] = (y - mu) * rsqrtf(var + LN_EPS);
    }
}

// ---------------- launch ----------------
extern "C" void kernel_launch(void* const* d_in, const int* in_sizes, int n_in,
                              void* d_out, int out_size) {
    const float* normed_x = (const float*)d_in[0];
    const float* conv_w   = (const float*)d_in[1];
    const float* conv_b   = (const float*)d_in[2];
    const float* pattern  = (const float*)d_in[3];
    const float* wq       = (const float*)d_in[4];
    const float* wkv      = (const float*)d_in[5];
    const float* wout     = (const float*)d_in[6];
    const float* bout     = (const float*)d_in[7];
    float* out = (float*)d_out;

    const int ATTN_SMEM = (32 * 64 + 512 * 36) * 4;   // 81920 B
    const int OUT_SMEM  = (512 * 36) * 4;             // 73728 B
    cudaFuncSetAttribute(k_attn, cudaFuncAttributeMaxDynamicSharedMemorySize, ATTN_SMEM);
    cudaFuncSetAttribute(k_out,  cudaFuncAttributeMaxDynamicSharedMemorySize, OUT_SMEM);

    k_prep<<<768, 256>>>(conv_w, wout);
    k_patkv<<<64, 256>>>(pattern, wkv);
    k_conv<<<2048, 256>>>(normed_x, conv_b);
    k_q<<<dim3(1024, 8), 256>>>(wq);
    k_attn<<<dim3(2048, 8), 256, ATTN_SMEM>>>();
    k_out<<<2048, 256, OUT_SMEM>>>(bout, out);
}

// round 2
// speedup vs baseline: 1.0021x; 1.0021x over previous
#include <cuda_runtime.h>
#include <cstdint>
#include <cstddef>

// Fixed problem dims (from setup_inputs)
#define TT      65536            // total rows (32 * 2048)
#define DD      256              // feature dim
#define PP      512              // patterns
#define HH      8                // heads
#define DA      64               // head dim
#define LSEQ    2048             // per-sequence length
#define LN_EPS  1e-5f

// ---------------- device scratch (no allocations allowed) ----------------
__device__ float g_wT[3 * DD * DD];            // [k][i][c]   transposed conv weights
__device__ float g_woT[(HH * DA) * DD];        // [j][c]      transposed wout
__device__ float g_xln[(size_t)TT * DD];       // conv+LN output (64 MB)
__device__ float g_q[(size_t)TT * (HH * DA)];  // q           (128 MB)
__device__ float g_att[(size_t)TT * (HH * DA)];// attn output (128 MB)
__device__ float g_kT[HH * DA * PP];           // [h][d][w]   pre-scaled by 1/8
__device__ float g_v[HH * PP * DA];            // [h][w][d]

// ---------------- helpers ----------------
__device__ __forceinline__ float2 blockSum2(float a, float b, float* red) {
    // 256 threads / 8 warps
    #pragma unroll
    for (int o = 16; o; o >>= 1) {
        a += __shfl_xor_sync(0xffffffffu, a, o);
        b += __shfl_xor_sync(0xffffffffu, b, o);
    }
    __syncthreads();  // protect red from reads of a previous call
    if ((threadIdx.x & 31) == 0) {
        red[threadIdx.x >> 5] = a;
        red[(threadIdx.x >> 5) + 8] = b;
    }
    __syncthreads();
    a = 0.f; b = 0.f;
    #pragma unroll
    for (int k = 0; k < 8; k++) { a += red[k]; b += red[k + 8]; }
    return make_float2(a, b);
}

// ---------------- K0: weight transposes ----------------
__global__ void __launch_bounds__(256) k_prep(const float* __restrict__ conv_w,
                                              const float* __restrict__ wout) {
    int idx = blockIdx.x * 256 + threadIdx.x;
    if (idx < 3 * DD * DD) {
        int c = idx / (DD * 3);
        int rem = idx % (DD * 3);
        int i = rem / 3, k = rem % 3;
        g_wT[(k * DD + i) * DD + c] = conv_w[idx];
    }
    if (idx < DD * (HH * DA)) {
        int c = idx >> 9, j = idx & 511;
        g_woT[j * DD + c] = wout[idx];
    }
}

// ---------------- K1: pattern double-LN + kv projection ----------------
// 64 blocks x 256 threads, 8 pattern rows per block
__global__ void __launch_bounds__(256) k_patkv(const float* __restrict__ pattern,
                                               const float* __restrict__ wkv) {
    __shared__ float sp[8][DD];
    __shared__ float red[16];
    int r0 = blockIdx.x * 8;
    int tid = threadIdx.x;

    for (int r = 0; r < 8; r++) {
        float v = pattern[(size_t)(r0 + r) * DD + tid];
        float2 s = blockSum2(v, v * v, red);
        float mu = s.x * (1.f / DD);
        float var = s.y * (1.f / DD) - mu * mu;
        v = (v - mu) * rsqrtf(var + LN_EPS);
        s = blockSum2(v, v * v, red);
        mu = s.x * (1.f / DD);
        var = s.y * (1.f / DD) - mu * mu;
        v = (v - mu) * rsqrtf(var + LN_EPS);
        sp[r][tid] = v;
    }
    __syncthreads();

    for (int m = 0; m < 4; m++) {
        int j = m * 256 + tid;                // 0..1023 output of kv
        float acc[8];
        #pragma unroll
        for (int r = 0; r < 8; r++) acc[r] = 0.f;
        const float* wr = wkv + (size_t)j * DD;
        for (int i = 0; i < DD; i++) {
            float w = wr[i];
            #pragma unroll
            for (int r = 0; r < 8; r++) acc[r] += w * sp[r][i];
        }
        int h = j >> 7, e = j & 127;          // kv.reshape(P, H, 2*dA)
        if (e < DA) {
            #pragma unroll
            for (int r = 0; r < 8; r++)
                g_kT[(h * DA + e) * PP + r0 + r] = 0.125f * acc[r];   // fold scale
        } else {
            int d = e - DA;
            #pragma unroll
            for (int r = 0; r < 8; r++)
                g_v[((size_t)h * PP + r0 + r) * DA + d] = acc[r];
        }
    }
}

// ---------------- K2: causal conv + bias + residual + leaky + LN ----------------
// 2048 blocks x 256 threads, 32 rows per block (blocks never straddle a sequence)
__global__ void __launch_bounds__(256) k_conv(const float* __restrict__ x,
                                              const float* __restrict__ bias) {
    __shared__ float xsT[DD][40];   // [channel][row 0..33], row 0 == t0-2
    __shared__ float red[16];
    int t0 = blockIdx.x * 32;
    int tid = threadIdx.x;
    int seq_start = t0 & ~(LSEQ - 1);

    #pragma unroll
    for (int rr = 0; rr < 34; rr++) {
        int gr = t0 - 2 + rr;
        xsT[tid][rr] = (gr >= seq_start) ? x[(size_t)gr * DD + tid] : 0.f;
    }
    __syncthreads();

    float acc[32];
    #pragma unroll
    for (int r = 0; r < 32; r++) acc[r] = 0.f;

    const float* w0 = g_wT;                 // tap for x[t-2]
    const float* w1 = g_wT + DD * DD;       // tap for x[t-1]
    const float* w2 = g_wT + 2 * DD * DD;   // tap for x[t]

    for (int i = 0; i < DD; i++) {
        float a0 = w0[i * DD + tid];
        float a1 = w1[i * DD + tid];
        float a2 = w2[i * DD + tid];
        float4 xq[9];
        const float4* xp = (const float4*)xsT[i];
        #pragma unroll
        for (int m = 0; m < 9; m++) xq[m] = xp[m];
        const float* xv = (const float*)xq;
        #pragma unroll
        for (int r = 0; r < 32; r++)
            acc[r] += a0 * xv[r] + a1 * xv[r + 1] + a2 * xv[r + 2];
    }

    float bv = bias[tid];
    for (int r = 0; r < 32; r++) {
        float y = acc[r] + bv + xsT[tid][r + 2];   // +bias +residual
        y = (y > 0.f) ? y : 0.01f * y;             // leaky relu
        float2 s = blockSum2(y, y * y, red);
        float mu = s.x * (1.f / DD);
        float var = s.y * (1.f / DD) - mu * mu;
        g_xln[(size_t)(t0 + r) * DD + tid] = (y - mu) * rsqrtf(var + LN_EPS);
    }
}

// ---------------- K3: q = xln @ wq^T  (65536x512, K=256) ----------------
// grid (1024, 8), 64x64 tile, 4x4 micro-tile per thread
__global__ void __launch_bounds__(256) k_q(const float* __restrict__ wq) {
    __shared__ float As[16][68];
    __shared__ float Bs[16][68];
    int bm = blockIdx.x * 64;
    int bn = blockIdx.y * 64;
    int tid = threadIdx.x;
    int tm = (tid >> 4) * 4;
    int tn = (tid & 15) * 4;
    int lr = tid >> 2;
    int lk = (tid & 3) * 4;

    float acc[4][4];
    #pragma unroll
    for (int i = 0; i < 4; i++)
        #pragma unroll
        for (int j = 0; j < 4; j++) acc[i][j] = 0.f;

    for (int k0 = 0; k0 < DD; k0 += 16) {
        float4 av = *(const float4*)&g_xln[(size_t)(bm + lr) * DD + k0 + lk];
        float4 bv = *(const float4*)&wq[(size_t)(bn + lr) * DD + k0 + lk];
        As[lk + 0][lr] = av.x; As[lk + 1][lr] = av.y;
        As[lk + 2][lr] = av.z; As[lk + 3][lr] = av.w;
        Bs[lk + 0][lr] = bv.x; Bs[lk + 1][lr] = bv.y;
        Bs[lk + 2][lr] = bv.z; Bs[lk + 3][lr] = bv.w;
        __syncthreads();
        #pragma unroll
        for (int kk = 0; kk < 16; kk++) {
            float a[4], b[4];
            #pragma unroll
            for (int u = 0; u < 4; u++) a[u] = As[kk][tm + u];
            #pragma unroll
            for (int u = 0; u < 4; u++) b[u] = Bs[kk][tn + u];
            #pragma unroll
            for (int i = 0; i < 4; i++)
                #pragma unroll
                for (int j = 0; j < 4; j++) acc[i][j] += a[i] * b[j];
        }
        __syncthreads();
    }
    #pragma unroll
    for (int i = 0; i < 4; i++)
        #pragma unroll
        for (int j = 0; j < 4; j++)
            g_q[(size_t)(bm + tm + i) * 512 + bn + tn + j] = acc[i][j];
}

// ---------------- K4: fused attention per (32 rows, head) ----------------
// grid (2048, 8) x 256 threads. scores in SMEM (transposed), softmax, attn@V
__global__ void __launch_bounds__(256) k_attn() {
    extern __shared__ float dsm[];
    float* qs  = dsm;                 // [32][64]
    float* ssT = dsm + 32 * 64;       // [512][36]  (scores transposed)

    int r0 = blockIdx.x * 32;
    int h  = blockIdx.y;
    int tid = threadIdx.x;

    for (int idx = tid; idx < 32 * 64; idx += 256) {
        int r = idx >> 6, d = idx & 63;
        qs[r * 64 + d] = g_q[(size_t)(r0 + r) * 512 + h * 64 + d];
    }
    __syncthreads();

    int rq = tid >> 5;     // 0..7  -> rows rq*4 .. rq*4+3
    int wc = tid & 31;
    const float* kT = g_kT + (size_t)h * DA * PP;   // [d][w], pre-scaled

    #pragma unroll 1
    for (int half = 0; half < 2; half++) {
        float acc[4][8];
        #pragma unroll
        for (int i = 0; i < 4; i++)
            #pragma unroll
            for (int j = 0; j < 8; j++) acc[i][j] = 0.f;
        for (int d = 0; d < DA; d++) {
            float q4[4];
            #pragma unroll
            for (int i = 0; i < 4; i++) q4[i] = qs[(rq * 4 + i) * 64 + d];
            const float* kp = kT + d * PP + half * 256 + wc;
            #pragma unroll
            for (int j = 0; j < 8; j++) {
                float kv = kp[j * 32];
                #pragma unroll
                for (int i = 0; i < 4; i++) acc[i][j] += q4[i] * kv;
            }
        }
        #pragma unroll
        for (int j = 0; j < 8; j++) {
            int w = half * 256 + j * 32 + wc;
            #pragma unroll
            for (int i = 0; i < 4; i++) ssT[w * 36 + rq * 4 + i] = acc[i][j];
        }
    }
    __syncthreads();

    // softmax per row over 512 patterns; warp wp handles rows wp*4..+3
    int wp = tid >> 5, lane = tid & 31;
    for (int rr = 0; rr < 4; rr++) {
        int r = wp * 4 + rr;
        float m = -1e30f;
        for (int w = lane; w < PP; w += 32) m = fmaxf(m, ssT[w * 36 + r]);
        #pragma unroll
        for (int o = 16; o; o >>= 1) m = fmaxf(m, __shfl_xor_sync(0xffffffffu, m, o));
        float s = 0.f;
        for (int w = lane; w < PP; w += 32) {
            float e = __expf(ssT[w * 36 + r] - m);
            ssT[w * 36 + r] = e;
            s += e;
        }
        #pragma unroll
        for (int o = 16; o; o >>= 1) s += __shfl_xor_sync(0xffffffffu, s, o);
        float inv = 1.f / s;
        for (int w = lane; w < PP; w += 32) ssT[w * 36 + r] *= inv;
    }
    __syncthreads();

    // attn @ V : thread -> rows rq*4..+3, d in {wc, wc+32}
    const float* vh = g_v + (size_t)h * PP * DA;
    float oacc[4][2];
    #pragma unroll
    for (int i = 0; i < 4; i++) { oacc[i][0] = 0.f; oacc[i][1] = 0.f; }
    for (int w = 0; w < PP; w++) {
        float4 a4 = *(const float4*)&ssT[w * 36 + rq * 4];
        float v0 = vh[w * DA + wc];
        float v1 = vh[w * DA + wc + 32];
        oacc[0][0] += a4.x * v0; oacc[0][1] += a4.x * v1;
        oacc[1][0] += a4.y * v0; oacc[1][1] += a4.y * v1;
        oacc[2][0] += a4.z * v0; oacc[2][1] += a4.z * v1;
        oacc[3][0] += a4.w * v0; oacc[3][1] += a4.w * v1;
    }
    #pragma unroll
    for (int i = 0; i < 4; i++) {
        g_att[(size_t)(r0 + rq * 4 + i) * 512 + h * 64 + wc]      = oacc[i][0];
        g_att[(size_t)(r0 + rq * 4 + i) * 512 + h * 64 + wc + 32] = oacc[i][1];
    }
}

// ---------------- K5: out = att @ wout^T + bout, then LN ----------------
// 2048 blocks x 256 threads, 32 rows per block
__global__ void __launch_bounds__(256) k_out(const float* __restrict__ bout,
                                             float* __restrict__ out) {
    extern __shared__ float asT[];   // [512][36]
    __shared__ float red[16];
    int r0 = blockIdx.x * 32;
    int tid = threadIdx.x;

    for (int idx = tid; idx < 32 * 512; idx += 256) {
        int r = idx >> 9, j = idx & 511;
        asT[j * 36 + r] = g_att[(size_t)(r0 + r) * 512 + j];
    }
    __syncthreads();

    float acc[32];
    #pragma unroll
    for (int r = 0; r < 32; r++) acc[r] = 0.f;

    for (int j = 0; j < 512; j++) {
        float w = g_woT[j * DD + tid];
        const float4* ap = (const float4*)&asT[j * 36];
        #pragma unroll
        for (int m = 0; m < 8; m++) {
            float4 a = ap[m];
            acc[m * 4 + 0] += w * a.x;
            acc[m * 4 + 1] += w * a.y;
            acc[m * 4 + 2] += w * a.z;
            acc[m * 4 + 3] += w * a.w;
        }
    }

    float bv = bout[tid];
    for (int r = 0; r < 32; r++) {
        float y = acc[r] + bv;
        float2 s = blockSum2(y, y * y, red);
        float mu = s.x * (1.f / DD);
        float var = s.y * (1.f / DD) - mu * mu;
        out[(size_t)(r0 + r) * DD + tid] = (y - mu) * rsqrtf(var + LN_EPS);
    }
}

// ---------------- launch ----------------
extern "C" void kernel_launch(void* const* d_in, const int* in_sizes, int n_in,
                              void* d_out, int out_size) {
    const float* normed_x = (const float*)d_in[0];
    const float* conv_w   = (const float*)d_in[1];
    const float* conv_b   = (const float*)d_in[2];
    const float* pattern  = (const float*)d_in[3];
    const float* wq       = (const float*)d_in[4];
    const float* wkv      = (const float*)d_in[5];
    const float* wout     = (const float*)d_in[6];
    const float* bout     = (const float*)d_in[7];
    float* out = (float*)d_out;

    const int ATTN_SMEM = (32 * 64 + 512 * 36) * 4;   // 81920 B
    const int OUT_SMEM  = (512 * 36) * 4;             // 73728 B
    cudaFuncSetAttribute(k_attn, cudaFuncAttributeMaxDynamicSharedMemorySize, ATTN_SMEM);
    cudaFuncSetAttribute(k_out,  cudaFuncAttributeMaxDynamicSharedMemorySize, OUT_SMEM);

    k_prep<<<768, 256>>>(conv_w, wout);
    k_patkv<<<64, 256>>>(pattern, wkv);
    k_conv<<<2048, 256>>>(normed_x, conv_b);
    k_q<<<dim3(1024, 8), 256>>>(wq);
    k_attn<<<dim3(2048, 8), 256, ATTN_SMEM>>>();
    k_out<<<2048, 256, OUT_SMEM>>>(bout, out);
}

// round 4
// speedup vs baseline: 3.6465x; 3.6388x over previous
#include <cuda_runtime.h>
#include <cstdint>
#include <cstddef>

#define DD 256
#define PP 512
#define TT 65536
#define LSEQ 2048
#define EPSL 1e-5f

__device__ float g_wcat[DD * 768];          // [o][tap*256+c], tf32
__device__ float g_wq[512 * DD];            // tf32
__device__ float g_wo[DD * 512];            // tf32
__device__ float g_xln[(size_t)TT * DD];    // conv y raw -> LN'd tf32
__device__ float g_q[(size_t)TT * 512];     // q raw fp32; later out-GEMM scratch (ldc 256)
__device__ float g_att[(size_t)TT * 512];   // attn out raw fp32
__device__ float g_k[8 * PP * 64];          // [h][w][d], scaled 1/8, tf32
__device__ float g_vT[8 * 64 * PP];         // [h][d][w], tf32

__device__ __forceinline__ float ftf(float x) {
    uint32_t u;
    asm("cvt.rna.tf32.f32 %0, %1;" : "=r"(u) : "f"(x));
    return __uint_as_float(u);
}
__device__ __forceinline__ float4 ftf4(float4 v) {
    v.x = ftf(v.x); v.y = ftf(v.y); v.z = ftf(v.z); v.w = ftf(v.w);
    return v;
}
__device__ __forceinline__ void mma8(float* c, const uint32_t* a, const uint32_t* b) {
    asm volatile(
        "mma.sync.aligned.m16n8k8.row.col.f32.tf32.tf32.f32 "
        "{%0,%1,%2,%3}, {%4,%5,%6,%7}, {%8,%9}, {%0,%1,%2,%3};"
        : "+f"(c[0]), "+f"(c[1]), "+f"(c[2]), "+f"(c[3])
        : "r"(a[0]), "r"(a[1]), "r"(a[2]), "r"(a[3]), "r"(b[0]), "r"(b[1]));
}
#define FB(p) __float_as_uint(p)

// ---------- K0: weight prep ----------
__global__ void __launch_bounds__(256) k_prep(const float* __restrict__ conv_w,
                                              const float* __restrict__ wq,
                                              const float* __restrict__ wout) {
    int idx = blockIdx.x * 256 + threadIdx.x;
    if (idx < DD * 768) {
        int o = idx / 768, col = idx % 768;
        g_wcat[idx] = ftf(conv_w[o * 768 + (col & 255) * 3 + (col >> 8)]);
    }
    if (idx < 512 * DD) g_wq[idx] = ftf(wq[idx]);
    if (idx < DD * 512) g_wo[idx] = ftf(wout[idx]);
}

// ---------- reductions ----------
__device__ __forceinline__ float2 bsum2(float a, float b, float* red) {
    #pragma unroll
    for (int o = 16; o; o >>= 1) {
        a += __shfl_xor_sync(0xffffffffu, a, o);
        b += __shfl_xor_sync(0xffffffffu, b, o);
    }
    __syncthreads();
    if ((threadIdx.x & 31) == 0) {
        red[threadIdx.x >> 5] = a;
        red[(threadIdx.x >> 5) + 8] = b;
    }
    __syncthreads();
    a = 0.f; b = 0.f;
    #pragma unroll
    for (int k = 0; k < 8; k++) { a += red[k]; b += red[k + 8]; }
    return make_float2(a, b);
}

// ---------- K1: pattern double-LN + kv projection ----------
__global__ void __launch_bounds__(256) k_patkv(const float* __restrict__ pattern,
                                               const float* __restrict__ wkv) {
    __shared__ float sp[8][DD];
    __shared__ float red[16];
    int r0 = blockIdx.x * 8, tid = threadIdx.x;
    for (int r = 0; r < 8; r++) {
        float v = pattern[(size_t)(r0 + r) * DD + tid];
        for (int it = 0; it < 2; it++) {
            float2 s = bsum2(v, v * v, red);
            float mu = s.x * (1.f / DD);
            v = (v - mu) * rsqrtf(s.y * (1.f / DD) - mu * mu + EPSL);
        }
        sp[r][tid] = v;
    }
    __syncthreads();
    for (int m = 0; m < 4; m++) {
        int j = m * 256 + tid;
        float acc[8];
        #pragma unroll
        for (int r = 0; r < 8; r++) acc[r] = 0.f;
        const float* wr = wkv + (size_t)j * DD;
        for (int i = 0; i < DD; i++) {
            float w = wr[i];
            #pragma unroll
            for (int r = 0; r < 8; r++) acc[r] += w * sp[r][i];
        }
        int h = j >> 7, e = j & 127;
        if (e < 64) {
            #pragma unroll
            for (int r = 0; r < 8; r++)
                g_k[((size_t)h * PP + r0 + r) * 64 + e] = ftf(0.125f * acc[r]);
        } else {
            #pragma unroll
            for (int r = 0; r < 8; r++)
                g_vT[((size_t)h * 64 + e - 64) * PP + r0 + r] = ftf(acc[r]);
        }
    }
}

// ---------- generic MMA GEMM: C[128,128-tile] = A[128,K] * B[N,K]^T ----------
// mode 0: conv (A = x, rows shifted per tap, masked, ftf)
// mode 1: q    (A = g_xln, already tf32)
// mode 2: out  (A = g_att, ftf)
__global__ void __launch_bounds__(256) k_gemm(const float* __restrict__ A,
                                              const float* __restrict__ B,
                                              float* __restrict__ C,
                                              int K, int lda, int ldc, int mode) {
    extern __shared__ float sm[];
    float* As = sm;               // [128][36]
    float* Bs = sm + 128 * 36;    // [128][36]
    int tid = threadIdx.x, lane = tid & 31, warp = tid >> 5;
    int qr = lane >> 2, qc = lane & 3;
    int wm = warp >> 1, wn = warp & 1;
    int t0 = blockIdx.x * 128, n0 = blockIdx.y * 128;
    int seq0 = t0 & ~(LSEQ - 1);

    float cacc[2][8][4];
    #pragma unroll
    for (int mt = 0; mt < 2; mt++)
        #pragma unroll
        for (int nt = 0; nt < 8; nt++)
            #pragma unroll
            for (int i = 0; i < 4; i++) cacc[mt][nt][i] = 0.f;

    for (int kc = 0; kc < K; kc += 32) {
        #pragma unroll
        for (int i = tid; i < 1024; i += 256) {
            int r = i >> 3, cc = i & 7;
            float4 v;
            if (mode == 0) {
                int t = t0 + r + (kc >> 8) - 2;
                if (t >= seq0)
                    v = ftf4(*(const float4*)(A + (size_t)t * 256 + (kc & 255) + cc * 4));
                else
                    v = make_float4(0.f, 0.f, 0.f, 0.f);
            } else {
                v = *(const float4*)(A + (size_t)(t0 + r) * lda + kc + cc * 4);
                if (mode == 2) v = ftf4(v);
            }
            *(float4*)(As + r * 36 + cc * 4) = v;
            *(float4*)(Bs + r * 36 + cc * 4) =
                *(const float4*)(B + (size_t)(n0 + r) * K + kc + cc * 4);
        }
        __syncthreads();
        #pragma unroll
        for (int ks = 0; ks < 4; ks++) {
            int k0 = ks * 8;
            uint32_t a[2][4], b[8][2];
            #pragma unroll
            for (int mt = 0; mt < 2; mt++) {
                int m0 = wm * 32 + mt * 16;
                a[mt][0] = FB(As[(m0 + qr) * 36 + k0 + qc]);
                a[mt][1] = FB(As[(m0 + qr + 8) * 36 + k0 + qc]);
                a[mt][2] = FB(As[(m0 + qr) * 36 + k0 + qc + 4]);
                a[mt][3] = FB(As[(m0 + qr + 8) * 36 + k0 + qc + 4]);
            }
            #pragma unroll
            for (int nt = 0; nt < 8; nt++) {
                int nb = wn * 64 + nt * 8;
                b[nt][0] = FB(Bs[(nb + qr) * 36 + k0 + qc]);
                b[nt][1] = FB(Bs[(nb + qr) * 36 + k0 + qc + 4]);
            }
            #pragma unroll
            for (int mt = 0; mt < 2; mt++)
                #pragma unroll
                for (int nt = 0; nt < 8; nt++) mma8(cacc[mt][nt], a[mt], b[nt]);
        }
        __syncthreads();
    }
    #pragma unroll
    for (int mt = 0; mt < 2; mt++)
        #pragma unroll
        for (int nt = 0; nt < 8; nt++) {
            int r = t0 + wm * 32 + mt * 16 + qr;
            int col = n0 + wn * 64 + nt * 8 + qc * 2;
            *(float2*)(C + (size_t)r * ldc + col) =
                make_float2(cacc[mt][nt][0], cacc[mt][nt][1]);
            *(float2*)(C + (size_t)(r + 8) * ldc + col) =
                make_float2(cacc[mt][nt][2], cacc[mt][nt][3]);
        }
}

// ---------- conv epilogue: +bias +residual +leaky +LN, tf32 out (in-place) ----------
__global__ void __launch_bounds__(256) k_convln(const float* __restrict__ x,
                                                const float* __restrict__ cbias) {
    __shared__ float red[16];
    int tid = threadIdx.x;
    float bv = cbias[tid];
    for (int r = 0; r < 8; r++) {
        size_t row = (size_t)blockIdx.x * 8 + r;
        float y = g_xln[row * DD + tid] + bv + x[row * DD + tid];
        y = y > 0.f ? y : 0.01f * y;
        float2 s = bsum2(y, y * y, red);
        float mu = s.x * (1.f / DD);
        float inv = rsqrtf(s.y * (1.f / DD) - mu * mu + EPSL);
        g_xln[row * DD + tid] = ftf((y - mu) * inv);
    }
}

// ---------- final epilogue: +bout, LN ----------
__global__ void __launch_bounds__(256) k_outln(const float* __restrict__ bout,
                                               float* __restrict__ out) {
    __shared__ float red[16];
    int tid = threadIdx.x;
    float bv = bout[tid];
    for (int r = 0; r < 8; r++) {
        size_t row = (size_t)blockIdx.x * 8 + r;
        float y = g_q[row * DD + tid] + bv;
        float2 s = bsum2(y, y * y, red);
        float mu = s.x * (1.f / DD);
        float inv = rsqrtf(s.y * (1.f / DD) - mu * mu + EPSL);
        out[row * DD + tid] = (y - mu) * inv;
    }
}

// ---------- fused attention per (128 rows, head) ----------
__global__ void __launch_bounds__(256) k_attn() {
    extern __shared__ float sm[];
    float* Aq = sm;                   // [128][68]
    float* Bk = Aq + 128 * 68;        // [128][68]
    float* P  = Bk + 128 * 68;        // [128][132]
    float* Bv = P + 128 * 132;        // [64][132]
    float* rs = Bv + 64 * 132;        // [128]
    int tid = threadIdx.x, lane = tid & 31, warp = tid >> 5;
    int qr = lane >> 2, qc = lane & 3;
    int wm = warp >> 1, wn = warp & 1;
    int t0 = blockIdx.x * 128, h = blockIdx.y;

    for (int i = tid; i < 2048; i += 256) {
        int r = i >> 4, cc = i & 15;
        *(float4*)(Aq + r * 68 + cc * 4) =
            ftf4(*(const float4*)(g_q + (size_t)(t0 + r) * 512 + h * 64 + cc * 4));
    }
    if (tid < 128) rs[tid] = 0.f;

    float oacc[2][4][4];
    #pragma unroll
    for (int mt = 0; mt < 2; mt++)
        #pragma unroll
        for (int nt = 0; nt < 4; nt++)
            #pragma unroll
            for (int i = 0; i < 4; i++) oacc[mt][nt][i] = 0.f;

    for (int c = 0; c < 4; c++) {
        __syncthreads();   // previous chunk's PV reads done
        for (int i = tid; i < 2048; i += 256) {
            int r = i >> 4, cc = i & 15;
            *(float4*)(Bk + r * 68 + cc * 4) =
                *(const float4*)(g_k + ((size_t)h * PP + c * 128 + r) * 64 + cc * 4);
        }
        for (int i = tid; i < 2048; i += 256) {
            int r = i >> 5, cc = i & 31;
            *(float4*)(Bv + r * 132 + cc * 4) =
                *(const float4*)(g_vT + ((size_t)h * 64 + r) * PP + c * 128 + cc * 4);
        }
        __syncthreads();

        // scores: S[128,128] = Aq * Bk^T, K=64
        float s[2][8][4];
        #pragma unroll
        for (int mt = 0; mt < 2; mt++)
            #pragma unroll
            for (int nt = 0; nt < 8; nt++)
                #pragma unroll
                for (int i = 0; i < 4; i++) s[mt][nt][i] = 0.f;
        #pragma unroll
        for (int ks = 0; ks < 8; ks++) {
            int k0 = ks * 8;
            uint32_t a[2][4], b[8][2];
            #pragma unroll
            for (int mt = 0; mt < 2; mt++) {
                int m0 = wm * 32 + mt * 16;
                a[mt][0] = FB(Aq[(m0 + qr) * 68 + k0 + qc]);
                a[mt][1] = FB(Aq[(m0 + qr + 8) * 68 + k0 + qc]);
                a[mt][2] = FB(Aq[(m0 + qr) * 68 + k0 + qc + 4]);
                a[mt][3] = FB(Aq[(m0 + qr + 8) * 68 + k0 + qc + 4]);
            }
            #pragma unroll
            for (int nt = 0; nt < 8; nt++) {
                int nb = wn * 64 + nt * 8;
                b[nt][0] = FB(Bk[(nb + qr) * 68 + k0 + qc]);
                b[nt][1] = FB(Bk[(nb + qr) * 68 + k0 + qc + 4]);
            }
            #pragma unroll
            for (int mt = 0; mt < 2; mt++)
                #pragma unroll
                for (int nt = 0; nt < 8; nt++) mma8(s[mt][nt], a[mt], b[nt]);
        }

        // exp + rowsum + store P (tf32)
        #pragma unroll
        for (int mt = 0; mt < 2; mt++) {
            int r = wm * 32 + mt * 16 + qr;
            float sum0 = 0.f, sum1 = 0.f;
            #pragma unroll
            for (int nt = 0; nt < 8; nt++) {
                float e0 = __expf(s[mt][nt][0]);
                float e1 = __expf(s[mt][nt][1]);
                float e2 = __expf(s[mt][nt][2]);
                float e3 = __expf(s[mt][nt][3]);
                sum0 += e0 + e1;
                sum1 += e2 + e3;
                int col = wn * 64 + nt * 8 + qc * 2;
                *(float2*)(P + r * 132 + col) = make_float2(ftf(e0), ftf(e1));
                *(float2*)(P + (r + 8) * 132 + col) = make_float2(ftf(e2), ftf(e3));
            }
            sum0 += __shfl_xor_sync(0xffffffffu, sum0, 1);
            sum0 += __shfl_xor_sync(0xffffffffu, sum0, 2);
            sum1 += __shfl_xor_sync(0xffffffffu, sum1, 1);
            sum1 += __shfl_xor_sync(0xffffffffu, sum1, 2);
            if (qc == 0) {
                atomicAdd(&rs[r], sum0);
                atomicAdd(&rs[r + 8], sum1);
            }
        }
        __syncthreads();

        // O += P[128,128] * Bv[64,128]^T
        #pragma unroll
        for (int ks = 0; ks < 16; ks++) {
            int k0 = ks * 8;
            uint32_t a[2][4], b[4][2];
            #pragma unroll
            for (int mt = 0; mt < 2; mt++) {
                int m0 = wm * 32 + mt * 16;
                a[mt][0] = FB(P[(m0 + qr) * 132 + k0 + qc]);
                a[mt][1] = FB(P[(m0 + qr + 8) * 132 + k0 + qc]);
                a[mt][2] = FB(P[(m0 + qr) * 132 + k0 + qc + 4]);
                a[mt][3] = FB(P[(m0 + qr + 8) * 132 + k0 + qc + 4]);
            }
            #pragma unroll
            for (int nt = 0; nt < 4; nt++) {
                int nb = wn * 32 + nt * 8;
                b[nt][0] = FB(Bv[(nb + qr) * 132 + k0 + qc]);
                b[nt][1] = FB(Bv[(nb + qr) * 132 + k0 + qc + 4]);
            }
            #pragma unroll
            for (int mt = 0; mt < 2; mt++)
                #pragma unroll
                for (int nt = 0; nt < 4; nt++) mma8(oacc[mt][nt], a[mt], b[nt]);
        }
    }
    __syncthreads();

    #pragma unroll
    for (int mt = 0; mt < 2; mt++)
        #pragma unroll
        for (int nt = 0; nt < 4; nt++) {
            int r = wm * 32 + mt * 16 + qr;
            int col = wn * 32 + nt * 8 + qc * 2;
            float i0 = 1.f / rs[r], i1 = 1.f / rs[r + 8];
            *(float2*)(g_att + (size_t)(t0 + r) * 512 + h * 64 + col) =
                make_float2(oacc[mt][nt][0] * i0, oacc[mt][nt][1] * i0);
            *(float2*)(g_att + (size_t)(t0 + r + 8) * 512 + h * 64 + col) =
                make_float2(oacc[mt][nt][2] * i1, oacc[mt][nt][3] * i1);
        }
}

extern "C" void kernel_launch(void* const* d_in, const int* in_sizes, int n_in,
                              void* d_out, int out_size) {
    const float* x      = (const float*)d_in[0];
    const float* conv_w = (const float*)d_in[1];
    const float* conv_b = (const float*)d_in[2];
    const float* pat    = (const float*)d_in[3];
    const float* wq     = (const float*)d_in[4];
    const float* wkv    = (const float*)d_in[5];
    const float* wout   = (const float*)d_in[6];
    const float* bout   = (const float*)d_in[7];
    float* out = (float*)d_out;

    const int GEMM_SMEM = 2 * 128 * 36 * 4;                       // 36864
    const int ATTN_SMEM = (128*68 + 128*68 + 128*132 + 64*132 + 128) * 4;  // 171520
    cudaFuncSetAttribute(k_attn, cudaFuncAttributeMaxDynamicSharedMemorySize, ATTN_SMEM);

    float* g_wcat_p; cudaGetSymbolAddress((void**)&g_wcat_p, g_wcat);
    float* g_wq_p;   cudaGetSymbolAddress((void**)&g_wq_p, g_wq);
    float* g_wo_p;   cudaGetSymbolAddress((void**)&g_wo_p, g_wo);
    float* g_xln_p;  cudaGetSymbolAddress((void**)&g_xln_p, g_xln);
    float* g_q_p;    cudaGetSymbolAddress((void**)&g_q_p, g_q);
    float* g_att_p;  cudaGetSymbolAddress((void**)&g_att_p, g_att);

    k_prep<<<768, 256>>>(conv_w, wq, wout);
    k_patkv<<<64, 256>>>(pat, wkv);
    k_gemm<<<dim3(512, 2), 256, GEMM_SMEM>>>(x, g_wcat_p, g_xln_p, 768, 256, 256, 0);
    k_convln<<<8192, 256>>>(x, conv_b);
    k_gemm<<<dim3(512, 4), 256, GEMM_SMEM>>>(g_xln_p, g_wq_p, g_q_p, 256, 256, 512, 1);
    k_attn<<<dim3(512, 8), 256, ATTN_SMEM>>>();
    k_gemm<<<dim3(512, 2), 256, GEMM_SMEM>>>(g_att_p, g_wo_p, g_q_p, 512, 512, 256, 2);
    k_outln<<<8192, 256>>>(bout, out);
}